// round 11
// baseline (speedup 1.0000x reference)
#include <cuda_runtime.h>

#define NN 768
#define LL 8
#define HH 64
#define RR (NN*LL)       // 6144 rows, row index = node*LL + l
#define FF 80            // features: 64 v | 4 cmv | 12 cmv*coord
#define HOUT (RR*HH)     // h-output floats before coord-output

// ---------------- scratch (device globals) -----------------------------------
__device__ __align__(16) float g_q[RR*HH];
__device__ __align__(16) float g_k[RR*HH];
__device__ __align__(16) float g_F[(size_t)LL*NN*FF];    // [l][j][80]
__device__ __align__(16) float g_sc[(size_t)LL*NN*NN];   // [l][i][j]
__device__ __align__(16) float g_part[(size_t)4*RR*FF];  // [js][row][80]

// ---------------- Kernel 1: MLPs, 3 planes (q | k | v+coord+F) ---------------

__device__ __forceinline__ void gemm_tile32(
    const float* __restrict__ A_s,   // [32][64] shared
    const float* __restrict__ W_s,   // [64][64] shared
    const float* __restrict__ bias,
    float* Cs, float* gout,
    int gr0, int tx, int ty)
{
    const int r0 = ty * 2, c0 = tx * 4;
    const float b0 = bias[c0+0], b1 = bias[c0+1], b2 = bias[c0+2], b3 = bias[c0+3];
    float a00=b0, a01=b1, a02=b2, a03=b3;
    float a10=b0, a11=b1, a12=b2, a13=b3;
#pragma unroll 16
    for (int kk = 0; kk < 64; kk++) {
        float4 w = *(const float4*)(W_s + kk*64 + c0);
        float x0 = A_s[(r0+0)*64 + kk];
        float x1 = A_s[(r0+1)*64 + kk];
        a00 += x0*w.x; a01 += x0*w.y; a02 += x0*w.z; a03 += x0*w.w;
        a10 += x1*w.x; a11 += x1*w.y; a12 += x1*w.z; a13 += x1*w.w;
    }
    a00 = fmaxf(a00, 0.f); a01 = fmaxf(a01, 0.f); a02 = fmaxf(a02, 0.f); a03 = fmaxf(a03, 0.f);
    a10 = fmaxf(a10, 0.f); a11 = fmaxf(a11, 0.f); a12 = fmaxf(a12, 0.f); a13 = fmaxf(a13, 0.f);
    if (Cs) {
        *(float4*)(Cs + (r0+0)*64 + c0) = make_float4(a00, a01, a02, a03);
        *(float4*)(Cs + (r0+1)*64 + c0) = make_float4(a10, a11, a12, a13);
    }
    if (gout) {
        *(float4*)(gout + (size_t)(gr0 + r0 + 0)*64 + c0) = make_float4(a00, a01, a02, a03);
        *(float4*)(gout + (size_t)(gr0 + r0 + 1)*64 + c0) = make_float4(a10, a11, a12, a13);
    }
}

__device__ __forceinline__ void loadW64(float* W_s, const float* __restrict__ w, int tid)
{
    for (int e = tid; e < 64*64; e += 256) W_s[e] = w[e];
}

__global__ __launch_bounds__(256) void mlp_kernel(
    const float* __restrict__ h,
    const float* __restrict__ coord,
    const float* __restrict__ wq1, const float* __restrict__ bq1,
    const float* __restrict__ wq2, const float* __restrict__ bq2,
    const float* __restrict__ wk1, const float* __restrict__ bk1,
    const float* __restrict__ wk2, const float* __restrict__ bk2,
    const float* __restrict__ wv1, const float* __restrict__ bv1,
    const float* __restrict__ wv2, const float* __restrict__ bv2,
    const float* __restrict__ wc1, const float* __restrict__ bc1,
    const float* __restrict__ wc2)
{
    __shared__ __align__(16) float h_s[32*64];
    __shared__ __align__(16) float W_s[64*64];
    __shared__ __align__(16) float T_s[32*64];
    __shared__ __align__(16) float V_s[32*64];
    __shared__ float cmv_s[32*4];

    const int tid = threadIdx.x;
    const int tx = tid & 15, ty = tid >> 4;
    const int gr0 = blockIdx.x * 32;
    const int plane = blockIdx.y;

    for (int e = tid; e < 32*64; e += 256) h_s[e] = h[(size_t)gr0*64 + e];

    if (plane == 0) {
        loadW64(W_s, wq1, tid); __syncthreads();
        gemm_tile32(h_s, W_s, bq1, T_s, nullptr, gr0, tx, ty); __syncthreads();
        loadW64(W_s, wq2, tid); __syncthreads();
        gemm_tile32(T_s, W_s, bq2, nullptr, g_q, gr0, tx, ty);
        return;
    }
    if (plane == 1) {
        loadW64(W_s, wk1, tid); __syncthreads();
        gemm_tile32(h_s, W_s, bk1, T_s, nullptr, gr0, tx, ty); __syncthreads();
        loadW64(W_s, wk2, tid); __syncthreads();
        gemm_tile32(T_s, W_s, bk2, nullptr, g_k, gr0, tx, ty);
        return;
    }
    // plane 2: v, coord mlp, F build
    loadW64(W_s, wv1, tid); __syncthreads();
    gemm_tile32(h_s, W_s, bv1, T_s, nullptr, gr0, tx, ty); __syncthreads();
    loadW64(W_s, wv2, tid); __syncthreads();
    gemm_tile32(T_s, W_s, bv2, V_s, nullptr, gr0, tx, ty); __syncthreads();
    loadW64(W_s, wc1, tid); __syncthreads();
    gemm_tile32(V_s, W_s, bc1, T_s, nullptr, gr0, tx, ty); __syncthreads();
    // cmv = T @ wc2 (64 -> 4, no bias/relu)
    if (tid < 128) {
        int r = tid >> 2, k = tid & 3;
        float s = 0.f;
#pragma unroll 16
        for (int c = 0; c < 64; c++) s += T_s[r*64 + c] * wc2[c*4 + k];
        cmv_s[r*4 + k] = s;
    }
    __syncthreads();
    // F[l][node][80] = [v | cmv | cmv*coord]
    for (int e = tid; e < 32*FF; e += 256) {
        int r = e / FF, f = e % FF;
        int grow = gr0 + r;              // node*LL + l
        int node = grow >> 3, l = grow & 7;
        float val;
        if (f < 64)      val = V_s[r*64 + f];
        else if (f < 68) val = cmv_s[r*4 + (f - 64)];
        else {
            int kt = f - 68;
            val = cmv_s[r*4 + kt/3] * coord[(size_t)grow*12 + kt];
        }
        g_F[((size_t)l*NN + node)*FF + f] = val;
    }
}

// ---------------- Kernel 2: scores, 64i x 128j tiles -------------------------
// 256 threads: ty in [0,16) -> 4 i-rows; tx in [0,16) -> 8 j-cols.

__global__ __launch_bounds__(256) void score_kernel()
{
    __shared__ __align__(16) float A_s[64*64];    // q [i][h]
    __shared__ __align__(16) float W_s[64*136];   // kT [h][j], pad 136 (16B-aligned rows)
    const int tid = threadIdx.x;
    const int tx = tid & 15, ty = tid >> 4;
    const int gj0 = blockIdx.x * 128;
    const int gi0 = blockIdx.y * 64;
    const int l   = blockIdx.z;

    for (int e = tid; e < 64*64; e += 256) {
        int a = e >> 6, hh = e & 63;
        A_s[e] = g_q[((size_t)(gi0 + a)*LL + l)*64 + hh];
    }
    for (int e = tid; e < 128*64; e += 256) {
        int a = e >> 6, hh = e & 63;
        W_s[hh*136 + a] = g_k[((size_t)(gj0 + a)*LL + l)*64 + hh];
    }
    __syncthreads();

    const int i0 = ty * 4, j0 = tx * 8;
    float acc[4][8];
#pragma unroll
    for (int i = 0; i < 4; i++)
#pragma unroll
        for (int j = 0; j < 8; j++) acc[i][j] = 0.f;

#pragma unroll 4
    for (int kk = 0; kk < 64; kk++) {
        float4 w0 = *(const float4*)(W_s + kk*136 + j0);
        float4 w1 = *(const float4*)(W_s + kk*136 + j0 + 4);
#pragma unroll
        for (int i = 0; i < 4; i++) {
            float a = A_s[(i0+i)*64 + kk];
            acc[i][0] += a*w0.x; acc[i][1] += a*w0.y; acc[i][2] += a*w0.z; acc[i][3] += a*w0.w;
            acc[i][4] += a*w1.x; acc[i][5] += a*w1.y; acc[i][6] += a*w1.z; acc[i][7] += a*w1.w;
        }
    }
#pragma unroll
    for (int i = 0; i < 4; i++) {
        float* dst = &g_sc[((size_t)l*NN + gi0 + i0 + i)*NN + gj0 + j0];
        *(float4*)dst       = make_float4(acc[i][0], acc[i][1], acc[i][2], acc[i][3]);
        *(float4*)(dst + 4) = make_float4(acc[i][4], acc[i][5], acc[i][6], acc[i][7]);
    }
}

// ---------------- Kernel 3: softmax over j, in place ------------------------

__global__ __launch_bounds__(256) void softmax_kernel()
{
    const int p = blockIdx.x;                // p = l*768 + i
    float* row = g_sc + (size_t)p * NN;
    const int tid = threadIdx.x;
    __shared__ float red[8];

    float x0 = row[tid], x1 = row[tid + 256], x2 = row[tid + 512];
    float m = fmaxf(fmaxf(x0, x1), x2);
#pragma unroll
    for (int o = 16; o; o >>= 1) m = fmaxf(m, __shfl_xor_sync(0xffffffffu, m, o));
    if ((tid & 31) == 0) red[tid >> 5] = m;
    __syncthreads();
    float M = red[0];
#pragma unroll
    for (int i = 1; i < 8; i++) M = fmaxf(M, red[i]);

    float e0 = __expf(x0 - M), e1 = __expf(x1 - M), e2 = __expf(x2 - M);
    float s = e0 + e1 + e2;
#pragma unroll
    for (int o = 16; o; o >>= 1) s += __shfl_xor_sync(0xffffffffu, s, o);
    __syncthreads();
    if ((tid & 31) == 0) red[tid >> 5] = s;
    __syncthreads();
    float S = 0.f;
#pragma unroll
    for (int i = 0; i < 8; i++) S += red[i];
    float inv = 1.0f / S;

    row[tid]       = e0 * inv;
    row[tid + 256] = e1 * inv;
    row[tid + 512] = e2 * inv;
}

// ---------------- Kernel 4: agg partials (split-j GEMM, 256 thr) ------------
// block: 32 i-rows x 80 f, one l, one of 4 j-splits (192 j each).
// 256 threads: tx in [0,16) covers f = {4tx..4tx+3, 64+tx}; ty in [0,16) -> 2 rows.

__global__ __launch_bounds__(256) void agg_kernel()
{
    __shared__ __align__(16) float A_s[32*65];   // alpha [i][j], pad 65
    __shared__ __align__(16) float W_s[64*80];   // F tile [j][f]
    const int tid = threadIdx.x;
    const int tx = tid & 15, ty = tid >> 4;
    const int gi0 = blockIdx.x * 32;
    const int l   = blockIdx.y;
    const int js  = blockIdx.z;
    const int r0  = ty * 2;

    float acc[2][5];
#pragma unroll
    for (int r = 0; r < 2; r++)
#pragma unroll
        for (int f = 0; f < 5; f++) acc[r][f] = 0.f;

    for (int jt = 0; jt < 3; jt++) {
        const int gj0 = js * 192 + jt * 64;
        for (int e = tid; e < 32*64; e += 256) {
            int i = e >> 6, j = e & 63;
            A_s[i*65 + j] = g_sc[((size_t)l*NN + gi0 + i)*NN + gj0 + j];
        }
        {
            const float4* src = (const float4*)g_F + ((size_t)l*NN + gj0)*(FF/4);
            float4* dst = (float4*)W_s;
            for (int e = tid; e < 64*(FF/4); e += 256) dst[e] = src[e];
        }
        __syncthreads();

#pragma unroll 4
        for (int j = 0; j < 64; j++) {
            float4 w = *(const float4*)(W_s + j*FF + tx*4);
            float ws = W_s[j*FF + 64 + tx];
#pragma unroll
            for (int r = 0; r < 2; r++) {
                float a = A_s[(r0+r)*65 + j];
                acc[r][0] += a*w.x; acc[r][1] += a*w.y;
                acc[r][2] += a*w.z; acc[r][3] += a*w.w;
                acc[r][4] += a*ws;
            }
        }
        __syncthreads();
    }

#pragma unroll
    for (int r = 0; r < 2; r++) {
        size_t row = (size_t)(gi0 + r0 + r)*LL + l;
        float* p = g_part + ((size_t)js*RR + row)*FF;
        *(float4*)(p + tx*4) = make_float4(acc[r][0], acc[r][1], acc[r][2], acc[r][3]);
        p[64 + tx] = acc[r][4];
    }
}

// ---------------- Kernel 5: reduce partials + epilogue ----------------------

__global__ __launch_bounds__(256) void reduce_kernel(
    const float* __restrict__ h_in,
    const float* __restrict__ coord,
    float* __restrict__ out)
{
    const int warp = threadIdx.x >> 5, lane = threadIdx.x & 31;
    const size_t row = (size_t)blockIdx.x * 8 + warp;
    const float* p0 = g_part + row * FF;

    float s1 = 0.f, s2 = 0.f, s3 = 0.f;
#pragma unroll
    for (int js = 0; js < 4; js++) {
        const float* p = p0 + (size_t)js * RR * FF;
        s1 += p[lane];
        s2 += p[32 + lane];
        if (lane < 16) s3 += p[64 + lane];
    }

    out[row*64 + lane]      = h_in[row*64 + lane]      + s1;
    out[row*64 + 32 + lane] = h_in[row*64 + 32 + lane] + s2;

    float S = __shfl_sync(0xffffffffu, s3, (lane / 3) & 3);
    float P = __shfl_sync(0xffffffffu, s3, (4 + lane) & 31);
    if (lane < 12) {
        float c = coord[row*12 + lane];
        out[HOUT + row*12 + lane] = fmaf(c, S, c) - P;
    }
}

// ---------------- launch -----------------------------------------------------

extern "C" void kernel_launch(void* const* d_in, const int* in_sizes, int n_in,
                              void* d_out, int out_size)
{
    const float* h     = (const float*)d_in[0];
    const float* coord = (const float*)d_in[1];
    const float* wq1 = (const float*)d_in[2];  const float* bq1 = (const float*)d_in[3];
    const float* wq2 = (const float*)d_in[4];  const float* bq2 = (const float*)d_in[5];
    const float* wk1 = (const float*)d_in[6];  const float* bk1 = (const float*)d_in[7];
    const float* wk2 = (const float*)d_in[8];  const float* bk2 = (const float*)d_in[9];
    const float* wv1 = (const float*)d_in[10]; const float* bv1 = (const float*)d_in[11];
    const float* wv2 = (const float*)d_in[12]; const float* bv2 = (const float*)d_in[13];
    const float* wc1 = (const float*)d_in[14]; const float* bc1 = (const float*)d_in[15];
    const float* wc2 = (const float*)d_in[16];
    float* out = (float*)d_out;

    mlp_kernel<<<dim3(RR/32, 3), 256>>>(h, coord, wq1, bq1, wq2, bq2, wk1, bk1, wk2, bk2,
                                        wv1, bv1, wv2, bv2, wc1, bc1, wc2);
    score_kernel<<<dim3(NN/128, NN/64, LL), 256>>>();
    softmax_kernel<<<RR, 256>>>();
    agg_kernel<<<dim3(NN/32, LL, 4), 256>>>();
    reduce_kernel<<<RR/8, 256>>>(h, coord, out);
}